// round 11
// baseline (speedup 1.0000x reference)
#include <cuda_runtime.h>
#include <cuda_bf16.h>
#include <cuda_fp16.h>
#include <cstdint>
#include <math_constants.h>

#define B_ROWS 65536
#define DIM    256
#define NEMB   1024
#define MARGIN 2.0f
#define NSPLIT 2
#define NB_PER 4          // 8 N-blocks / NSPLIT

// ---------------------------------------------------------------------------
// Scratch (__device__ globals; no allocations)
// ---------------------------------------------------------------------------
__device__ float          g_xnorm[B_ROWS];
__device__ float          g_enorm[NEMB];
__device__ __nv_bfloat16  g_xb[(size_t)B_ROWS * DIM];
__device__ __nv_bfloat16  g_eb[(size_t)NEMB * DIM];
__device__ __half         g_dist_h[(size_t)B_ROWS * NEMB];  // 134 MB approx distances
__device__ float          g_bmin[(size_t)B_ROWS * 8];       // per-row per-128-block min (2 MB)

// ---------------------------------------------------------------------------
// PTX helpers (arch-agnostic sm_80 features only)
// ---------------------------------------------------------------------------
__device__ __forceinline__ uint32_t smem_u32(const void* p) {
    uint32_t a;
    asm("{ .reg .u64 t; cvta.to.shared.u64 t, %1; cvt.u32.u64 %0, t; }" : "=r"(a) : "l"(p));
    return a;
}
__device__ __forceinline__ void cp_async16(uint32_t dst, const void* src) {
    asm volatile("cp.async.cg.shared.global [%0], [%1], 16;" :: "r"(dst), "l"(src));
}
#define CP_COMMIT() asm volatile("cp.async.commit_group;" ::: "memory")
#define CP_WAIT(n)  asm volatile("cp.async.wait_group %0;" :: "n"(n) : "memory")

__device__ __forceinline__ void ldsm_x4(uint32_t* r, uint32_t addr) {
    asm volatile("ldmatrix.sync.aligned.m8n8.x4.shared.b16 {%0,%1,%2,%3}, [%4];"
                 : "=r"(r[0]), "=r"(r[1]), "=r"(r[2]), "=r"(r[3]) : "r"(addr) : "memory");
}
__device__ __forceinline__ void mma_bf16(float* c, const uint32_t* a, const uint32_t* b) {
    asm volatile("mma.sync.aligned.m16n8k16.row.col.f32.bf16.bf16.f32 "
                 "{%0,%1,%2,%3}, {%4,%5,%6,%7}, {%8,%9}, {%0,%1,%2,%3};"
                 : "+f"(c[0]), "+f"(c[1]), "+f"(c[2]), "+f"(c[3])
                 : "r"(a[0]), "r"(a[1]), "r"(a[2]), "r"(a[3]), "r"(b[0]), "r"(b[1]));
}

// ---------------------------------------------------------------------------
// Prep: fp32 -> bf16 + exact fp32 row norms. One warp per row; blocks past
// the x range handle the embedding rows.
// ---------------------------------------------------------------------------
__global__ void prep_kernel(const float* __restrict__ x, const float* __restrict__ e) {
    int gw = blockIdx.x * 8 + (threadIdx.x >> 5);
    int lane = threadIdx.x & 31;
    const float* src;
    uint2* dst;
    float* nrm;
    if (gw < B_ROWS) {
        src = x + (size_t)gw * DIM;
        dst = (uint2*)(g_xb + (size_t)gw * DIM);
        nrm = g_xnorm + gw;
    } else {
        int m = gw - B_ROWS;
        if (m >= NEMB) return;
        src = e + (size_t)m * DIM;
        dst = (uint2*)(g_eb + (size_t)m * DIM);
        nrm = g_enorm + m;
    }
    const float4* sr = (const float4*)src;
    float s = 0.f;
#pragma unroll
    for (int i = 0; i < 2; i++) {
        int f = lane + i * 32;
        float4 v = sr[f];
        s += v.x * v.x + v.y * v.y + v.z * v.z + v.w * v.w;
        __nv_bfloat162 lo = __floats2bfloat162_rn(v.x, v.y);
        __nv_bfloat162 hi = __floats2bfloat162_rn(v.z, v.w);
        uint2 pk;
        pk.x = *(unsigned*)&lo; pk.y = *(unsigned*)&hi;
        dst[f] = pk;
    }
#pragma unroll
    for (int o = 16; o; o >>= 1) s += __shfl_xor_sync(0xFFFFFFFFu, s, o);
    if (lane == 0) *nrm = s;
}

// ---------------------------------------------------------------------------
// bf16 HMMA GEMM: approx distances -> fp16 + per-row per-128-block mins.
// Grid = (512, 2), 256 threads (8 warps, 2(M) x 4(N), warp tile 64x32 —
// the validated round-8 shape with minimal ldsm/MMA ratio). NEW: fragment
// double-buffering — ks+1's 6 ldsm issue before ks's 16 MMAs, hiding ldsm
// latency (round-9 ncu: latency-bound, tensor<50%, issue ~20%).
// SMEM rows 512B, 16B chunk c at c ^ (row & 7) (conflict-free).
// ---------------------------------------------------------------------------
#define SMEM_A_OFF    0
#define SMEM_B_OFF    65536
#define SMEM_EN_OFF   196608
#define SMEM_XN_OFF   198656
#define SMEM_BMIN_OFF 199168
#define GEMM_SMEM     201216

__global__ __launch_bounds__(256, 1) void gemm_dist_kernel() {
    extern __shared__ char smem[];
    const uint32_t sb = smem_u32(smem);
    const int tid = threadIdx.x, lane = tid & 31, wid = tid >> 5;
    const int warp_m = wid >> 2, warp_n = wid & 3;
    const int m0 = blockIdx.x * 128;
    const int n0 = blockIdx.y * (NEMB / NSPLIT);

    float* s_en = (float*)(smem + SMEM_EN_OFF);
    float* s_xn = (float*)(smem + SMEM_XN_OFF);
    unsigned (*s_bmin)[128] = (unsigned(*)[128])(smem + SMEM_BMIN_OFF);
    for (int i = tid; i < NEMB / NSPLIT; i += 256) s_en[i] = g_enorm[n0 + i];
    if (tid < 128) s_xn[tid] = g_xnorm[m0 + tid];
    for (int i = tid; i < NB_PER * 128; i += 256)
        ((unsigned*)(smem + SMEM_BMIN_OFF))[i] = 0x7F800000u;   // +inf

    // A tile (once) + B blocks 0,1 of this half (two cp.async groups)
    {
        const __nv_bfloat16* Asrc = g_xb + (size_t)m0 * DIM;
        const __nv_bfloat16* Bsrc = g_eb + (size_t)n0 * DIM;
        for (int i = tid; i < 4096; i += 256) {
            int row = i >> 5, c = i & 31;
            cp_async16(sb + SMEM_A_OFF + row * 512 + ((c ^ (row & 7)) * 16),
                       Asrc + row * DIM + c * 8);
        }
        for (int i = tid; i < 4096; i += 256) {
            int row = i >> 5, c = i & 31;
            cp_async16(sb + SMEM_B_OFF + row * 512 + ((c ^ (row & 7)) * 16),
                       Bsrc + row * DIM + c * 8);
        }
        CP_COMMIT();
        for (int i = tid; i < 4096; i += 256) {
            int row = i >> 5, c = i & 31;
            cp_async16(sb + SMEM_B_OFF + 65536 + row * 512 + ((c ^ (row & 7)) * 16),
                       Bsrc + 128 * DIM + row * DIM + c * 8);
        }
        CP_COMMIT();
    }

    const int grp = lane >> 2, qc = (lane & 3) * 2;
    // Precomputed fragment address components
    const int a_row_l = lane & 15;
    const int a_kh    = lane >> 4;
    const int b_row_l = (lane & 7) + ((lane >> 4) & 1) * 8;
    const int b_kh    = (lane >> 3) & 1;

#pragma unroll 1
    for (int nb = 0; nb < NB_PER; nb++) {
        if (nb < NB_PER - 1) { CP_WAIT(1); } else { CP_WAIT(0); }
        __syncthreads();

        const uint32_t Abase = sb + SMEM_A_OFF;
        const uint32_t Bbase = sb + SMEM_B_OFF + (nb & 1) * 65536;

        float acc[4][4][4];
#pragma unroll
        for (int t = 0; t < 4; t++)
#pragma unroll
            for (int u = 0; u < 4; u++)
#pragma unroll
                for (int v = 0; v < 4; v++) acc[t][u][v] = 0.f;

        // Fragment double buffers
        uint32_t afr[2][4][4], bfr[2][2][4];

        // Preload ks = 0
        {
            int c = a_kh;
#pragma unroll
            for (int t = 0; t < 4; t++) {
                int row = warp_m * 64 + t * 16 + a_row_l;
                ldsm_x4(afr[0][t], Abase + row * 512 + ((c ^ (row & 7)) * 16));
            }
            int cb = b_kh;
#pragma unroll
            for (int p = 0; p < 2; p++) {
                int row = warp_n * 32 + p * 16 + b_row_l;
                ldsm_x4(bfr[0][p], Bbase + row * 512 + ((cb ^ (row & 7)) * 16));
            }
        }

#pragma unroll
        for (int ks = 0; ks < 16; ks++) {
            const int cur = ks & 1, nxt = cur ^ 1;
            if (ks < 15) {
                int c = (ks + 1) * 2 + a_kh;
#pragma unroll
                for (int t = 0; t < 4; t++) {
                    int row = warp_m * 64 + t * 16 + a_row_l;
                    ldsm_x4(afr[nxt][t], Abase + row * 512 + ((c ^ (row & 7)) * 16));
                }
                int cb = (ks + 1) * 2 + b_kh;
#pragma unroll
                for (int p = 0; p < 2; p++) {
                    int row = warp_n * 32 + p * 16 + b_row_l;
                    ldsm_x4(bfr[nxt][p], Bbase + row * 512 + ((cb ^ (row & 7)) * 16));
                }
            }
#pragma unroll
            for (int t = 0; t < 4; t++)
#pragma unroll
                for (int u = 0; u < 4; u++)
                    mma_bf16(acc[t][u], afr[cur][t], &bfr[cur][u >> 1][(u & 1) * 2]);
        }
        __syncthreads();   // all warps done reading this B buffer

        // Prefetch B block nb+2 of this half into the freed buffer.
        if (nb + 2 < NB_PER) {
            const __nv_bfloat16* Bsrc = g_eb + (size_t)(n0 + (nb + 2) * 128) * DIM;
            uint32_t Bdst = sb + SMEM_B_OFF + (nb & 1) * 65536;
            for (int i = tid; i < 4096; i += 256) {
                int row = i >> 5, c = i & 31;
                cp_async16(Bdst + row * 512 + ((c ^ (row & 7)) * 16),
                           Bsrc + row * DIM + c * 8);
            }
            CP_COMMIT();
        }

        // Epilogue: d = xn + en - 2*dot -> fp16 stores + per-block row mins.
#pragma unroll
        for (int t = 0; t < 4; t++) {
            int r0 = warp_m * 64 + t * 16 + grp;
            int r1 = r0 + 8;
            float xn0 = s_xn[r0], xn1 = s_xn[r1];
            float bm0 = CUDART_INF_F, bm1 = CUDART_INF_F;
#pragma unroll
            for (int u = 0; u < 4; u++) {
                int nl = nb * 128 + warp_n * 32 + u * 8 + qc;
                int ng = n0 + nl;
                float en0 = s_en[nl], en1 = s_en[nl + 1];
                float d0 = fmaf(-2.f, acc[t][u][0], xn0 + en0);
                float d1 = fmaf(-2.f, acc[t][u][1], xn0 + en1);
                float d2 = fmaf(-2.f, acc[t][u][2], xn1 + en0);
                float d3 = fmaf(-2.f, acc[t][u][3], xn1 + en1);
                bm0 = fminf(bm0, fminf(d0, d1));
                bm1 = fminf(bm1, fminf(d2, d3));
                *(__half2*)(g_dist_h + (size_t)(m0 + r0) * NEMB + ng) = __floats2half2_rn(d0, d1);
                *(__half2*)(g_dist_h + (size_t)(m0 + r1) * NEMB + ng) = __floats2half2_rn(d2, d3);
            }
            atomicMin(&s_bmin[nb][r0], __float_as_uint(fmaxf(bm0, 0.f)));
            atomicMin(&s_bmin[nb][r1], __float_as_uint(fmaxf(bm1, 0.f)));
        }
    }

    // Store block mins (clamped; float bits monotonic for >= 0).
    __syncthreads();
    if (tid < 128) {
        float* bp = g_bmin + (size_t)(m0 + tid) * 8 + blockIdx.y * NB_PER;
#pragma unroll
        for (int j = 0; j < NB_PER; j++)
            bp[j] = __uint_as_float(s_bmin[j][tid]);
    }
}

// ---------------------------------------------------------------------------
// Select + refine + outputs. One warp per row. Reads 8 block-mins, loads only
// the (typically 1) dist blocks that can contain margin-candidates, exact
// fp32 refine, outputs. Full-scan fallback if cand list overflows.
// ---------------------------------------------------------------------------
__global__ __launch_bounds__(256) void select_output_kernel(const float* __restrict__ x,
                                                            const float* __restrict__ Emb,
                                                            float* __restrict__ out) {
    const int wid = threadIdx.x >> 5, lane = threadIdx.x & 31;
    const int m = blockIdx.x * 8 + wid;

    __shared__ int s_cnt[8];
    __shared__ int s_cand[8][16];
    if (lane == 0) s_cnt[wid] = 0;
    __syncwarp();

    // Block mins -> global approx min (clamped) -> threshold + block mask.
    float b = (lane < 8) ? g_bmin[(size_t)m * 8 + lane] : CUDART_INF_F;
    float gmin = b;
#pragma unroll
    for (int o = 16; o; o >>= 1) gmin = fminf(gmin, __shfl_xor_sync(0xFFFFFFFFu, gmin, o));
    const float thr = gmin + MARGIN;
    unsigned bmask = __ballot_sync(0xFFFFFFFFu, lane < 8 && b <= thr);

    // Scan only flagged 128-col blocks for candidates.
    while (bmask) {
        int j = __ffs(bmask) - 1;
        bmask &= bmask - 1;
        const __half2* bp = (const __half2*)(g_dist_h + (size_t)m * NEMB + j * 128);
#pragma unroll
        for (int i = 0; i < 2; i++) {
            float2 f2 = __half22float2(bp[lane + i * 32]);
            int col = j * 128 + (lane + i * 32) * 2;
            if (f2.x <= thr) {
                int pos = atomicAdd(&s_cnt[wid], 1);
                if (pos < 16) s_cand[wid][pos] = col;
            }
            if (f2.y <= thr) {
                int pos = atomicAdd(&s_cnt[wid], 1);
                if (pos < 16) s_cand[wid][pos] = col + 1;
            }
        }
    }
    __syncwarp();
    const int cnt = s_cnt[wid];
    const bool fallback = cnt > 16;      // rare; exact full scan
    const int ncand = fallback ? NEMB : cnt;

    const float4* xr = (const float4*)(x + (size_t)m * DIM);
    float4 xv0 = xr[lane], xv1 = xr[lane + 32];
    const float xn = g_xnorm[m];

    unsigned long long best = 0xFFFFFFFFFFFFFFFFULL;
    for (int t = 0; t < ncand; t++) {
        const int col = fallback ? t : s_cand[wid][t];
        const float4* er = (const float4*)(Emb + (size_t)col * DIM);
        float4 e0 = er[lane], e1 = er[lane + 32];
        float p = 0.f;
        p = fmaf(xv0.x, e0.x, p); p = fmaf(xv0.y, e0.y, p);
        p = fmaf(xv0.z, e0.z, p); p = fmaf(xv0.w, e0.w, p);
        p = fmaf(xv1.x, e1.x, p); p = fmaf(xv1.y, e1.y, p);
        p = fmaf(xv1.z, e1.z, p); p = fmaf(xv1.w, e1.w, p);
#pragma unroll
        for (int o = 16; o; o >>= 1) p += __shfl_xor_sync(0xFFFFFFFFu, p, o);
        float d = fmaxf(xn + g_enorm[col] - 2.f * p, 0.f);
        unsigned long long key = ((unsigned long long)__float_as_uint(d) << 32) | (unsigned)col;
        best = key < best ? key : best;
    }
    const unsigned idx = (unsigned)(best & 0xFFFFFFFFULL);

    // Outputs: loss | quantized_st | onehot.
    const float4* er = (const float4*)(Emb + (size_t)idx * DIM);
    float4* lossp = (float4*)out + (size_t)m * (DIM / 4);
    float4* qp    = (float4*)(out + (size_t)B_ROWS * DIM) + (size_t)m * (DIM / 4);
    float4* ohp   = (float4*)(out + 2ull * B_ROWS * DIM) + (size_t)m * (NEMB / 4);

#pragma unroll
    for (int i = 0; i < 2; i++) {
        int f = lane + i * 32;
        float4 xvv = (i == 0) ? xv0 : xv1;
        float4 ev = er[f];
        float4 dl, ls, q;
        dl.x = ev.x - xvv.x; dl.y = ev.y - xvv.y; dl.z = ev.z - xvv.z; dl.w = ev.w - xvv.w;
        q.x = xvv.x + dl.x; q.y = xvv.y + dl.y; q.z = xvv.z + dl.z; q.w = xvv.w + dl.w;
        ls.x = 0.25f * dl.x * dl.x; ls.y = 0.25f * dl.y * dl.y;
        ls.z = 0.25f * dl.z * dl.z; ls.w = 0.25f * dl.w * dl.w;
        lossp[f] = ls;
        qp[f] = q;
    }
    const unsigned hot4 = idx >> 2, comp = idx & 3;
#pragma unroll
    for (int i = lane; i < NEMB / 4; i += 32) {
        float4 z = make_float4(0.f, 0.f, 0.f, 0.f);
        if ((unsigned)i == hot4) ((float*)&z)[comp] = 1.0f;
        ohp[i] = z;
    }
}

// ---------------------------------------------------------------------------
extern "C" void kernel_launch(void* const* d_in, const int* in_sizes, int n_in,
                              void* d_out, int out_size) {
    const float* x;
    const float* e;
    if (in_sizes[0] == B_ROWS * DIM) {
        x = (const float*)d_in[0];
        e = (const float*)d_in[1];
    } else {
        x = (const float*)d_in[1];
        e = (const float*)d_in[0];
    }
    float* out = (float*)d_out;

    static bool init_done = false;
    if (!init_done) {
        cudaFuncSetAttribute(gemm_dist_kernel,
                             cudaFuncAttributeMaxDynamicSharedMemorySize, GEMM_SMEM);
        init_done = true;
    }

    prep_kernel<<<(B_ROWS + NEMB) / 8, 256>>>(x, e);

    dim3 ggrid(B_ROWS / 128, NSPLIT);   // 512 x 2 = 1024 CTAs
    gemm_dist_kernel<<<ggrid, 256, GEMM_SMEM>>>();

    select_output_kernel<<<B_ROWS / 8, 256>>>(x, e, out);
}

// round 12
// speedup vs baseline: 1.3576x; 1.3576x over previous
#include <cuda_runtime.h>
#include <cuda_bf16.h>
#include <cuda_fp16.h>
#include <cstdint>

#define B_ROWS 65536
#define DIM    256
#define NEMB   1024
#define MARGIN 2.0f
#define NSPLIT 2
#define NB_PER 4          // 8 N-blocks / NSPLIT

// ---------------------------------------------------------------------------
// Scratch (__device__ globals; no allocations)
// ---------------------------------------------------------------------------
__device__ float          g_xnorm[B_ROWS];
__device__ float          g_enorm[NEMB];
__device__ __nv_bfloat16  g_xb[(size_t)B_ROWS * DIM];
__device__ __nv_bfloat16  g_eb[(size_t)NEMB * DIM];
__device__ __half         g_dist_h[(size_t)B_ROWS * NEMB];   // 134 MB approx distances

// ---------------------------------------------------------------------------
// PTX helpers (arch-agnostic sm_80 features only)
// ---------------------------------------------------------------------------
__device__ __forceinline__ uint32_t smem_u32(const void* p) {
    uint32_t a;
    asm("{ .reg .u64 t; cvta.to.shared.u64 t, %1; cvt.u32.u64 %0, t; }" : "=r"(a) : "l"(p));
    return a;
}
__device__ __forceinline__ void cp_async16(uint32_t dst, const void* src) {
    asm volatile("cp.async.cg.shared.global [%0], [%1], 16;" :: "r"(dst), "l"(src));
}
#define CP_COMMIT() asm volatile("cp.async.commit_group;" ::: "memory")
#define CP_WAIT(n)  asm volatile("cp.async.wait_group %0;" :: "n"(n) : "memory")

__device__ __forceinline__ void ldsm_x4(uint32_t* r, uint32_t addr) {
    asm volatile("ldmatrix.sync.aligned.m8n8.x4.shared.b16 {%0,%1,%2,%3}, [%4];"
                 : "=r"(r[0]), "=r"(r[1]), "=r"(r[2]), "=r"(r[3]) : "r"(addr) : "memory");
}
__device__ __forceinline__ void mma_bf16(float* c, const uint32_t* a, const uint32_t* b) {
    asm volatile("mma.sync.aligned.m16n8k16.row.col.f32.bf16.bf16.f32 "
                 "{%0,%1,%2,%3}, {%4,%5,%6,%7}, {%8,%9}, {%0,%1,%2,%3};"
                 : "+f"(c[0]), "+f"(c[1]), "+f"(c[2]), "+f"(c[3])
                 : "r"(a[0]), "r"(a[1]), "r"(a[2]), "r"(a[3]), "r"(b[0]), "r"(b[1]));
}

// ---------------------------------------------------------------------------
// Prep: fp32 -> bf16 + exact fp32 row norms. One warp per row; blocks past
// the x range handle the embedding rows.
// ---------------------------------------------------------------------------
__global__ void prep_kernel(const float* __restrict__ x, const float* __restrict__ e) {
    int gw = blockIdx.x * 8 + (threadIdx.x >> 5);
    int lane = threadIdx.x & 31;
    const float* src;
    uint2* dst;
    float* nrm;
    if (gw < B_ROWS) {
        src = x + (size_t)gw * DIM;
        dst = (uint2*)(g_xb + (size_t)gw * DIM);
        nrm = g_xnorm + gw;
    } else {
        int m = gw - B_ROWS;
        if (m >= NEMB) return;
        src = e + (size_t)m * DIM;
        dst = (uint2*)(g_eb + (size_t)m * DIM);
        nrm = g_enorm + m;
    }
    const float4* sr = (const float4*)src;
    float s = 0.f;
#pragma unroll
    for (int i = 0; i < 2; i++) {
        int f = lane + i * 32;
        float4 v = sr[f];
        s += v.x * v.x + v.y * v.y + v.z * v.z + v.w * v.w;
        __nv_bfloat162 lo = __floats2bfloat162_rn(v.x, v.y);
        __nv_bfloat162 hi = __floats2bfloat162_rn(v.z, v.w);
        uint2 pk;
        pk.x = *(unsigned*)&lo; pk.y = *(unsigned*)&hi;
        dst[f] = pk;
    }
#pragma unroll
    for (int o = 16; o; o >>= 1) s += __shfl_xor_sync(0xFFFFFFFFu, s, o);
    if (lane == 0) *nrm = s;
}

// ---------------------------------------------------------------------------
// Onehot zero-fill: 268 MB of idx-independent zeros, launched on a second
// stream to run concurrently with the GEMM (which leaves DRAM and registers
// idle: 16 regs x 256 thr co-resides beside the 192-reg GEMM CTA).
// ---------------------------------------------------------------------------
__global__ __launch_bounds__(256) void zero_onehot_kernel(float* __restrict__ out) {
    float4* p = (float4*)(out + 2ull * B_ROWS * DIM);
    size_t i = (size_t)blockIdx.x * 2048 + threadIdx.x;   // 8 float4 per thread
    const float4 z = make_float4(0.f, 0.f, 0.f, 0.f);
#pragma unroll
    for (int k = 0; k < 8; k++) p[i + (size_t)k * 256] = z;
}

// ---------------------------------------------------------------------------
// bf16 HMMA GEMM: approx distances -> fp16 (byte-identical to round-8 winner).
// Grid = (512, 2): 128-row M block x 512-code N half; 1024 CTAs -> 1.2% wave
// tail. A tile SMEM-resident; 4 N-blocks of 128 codes, cp.async double-
// buffered B. 8 warps 2(M) x 4(N), warp tile 64x32, mma.m16n8k16 bf16->fp32.
// SMEM rows 512B; 16B chunk c stored at c ^ (row & 7) (conflict-free).
// ---------------------------------------------------------------------------
#define SMEM_A_OFF  0
#define SMEM_B_OFF  65536
#define SMEM_EN_OFF 196608
#define SMEM_XN_OFF 200704
#define GEMM_SMEM   201216

__global__ __launch_bounds__(256, 1) void gemm_dist_kernel() {
    extern __shared__ char smem[];
    const uint32_t sb = smem_u32(smem);
    const int tid = threadIdx.x, lane = tid & 31, wid = tid >> 5;
    const int warp_m = wid >> 2, warp_n = wid & 3;
    const int m0 = blockIdx.x * 128;
    const int n0 = blockIdx.y * (NEMB / NSPLIT);

    float* s_en = (float*)(smem + SMEM_EN_OFF);
    float* s_xn = (float*)(smem + SMEM_XN_OFF);
    for (int i = tid; i < NEMB / NSPLIT; i += 256) s_en[i] = g_enorm[n0 + i];
    if (tid < 128) s_xn[tid] = g_xnorm[m0 + tid];

    // A tile (once) + B blocks 0,1 of this half (two cp.async groups)
    {
        const __nv_bfloat16* Asrc = g_xb + (size_t)m0 * DIM;
        const __nv_bfloat16* Bsrc = g_eb + (size_t)n0 * DIM;
        for (int i = tid; i < 4096; i += 256) {
            int row = i >> 5, c = i & 31;
            cp_async16(sb + SMEM_A_OFF + row * 512 + ((c ^ (row & 7)) * 16),
                       Asrc + row * DIM + c * 8);
        }
        for (int i = tid; i < 4096; i += 256) {
            int row = i >> 5, c = i & 31;
            cp_async16(sb + SMEM_B_OFF + row * 512 + ((c ^ (row & 7)) * 16),
                       Bsrc + row * DIM + c * 8);
        }
        CP_COMMIT();
        for (int i = tid; i < 4096; i += 256) {
            int row = i >> 5, c = i & 31;
            cp_async16(sb + SMEM_B_OFF + 65536 + row * 512 + ((c ^ (row & 7)) * 16),
                       Bsrc + 128 * DIM + row * DIM + c * 8);
        }
        CP_COMMIT();
    }

    const int grp = lane >> 2, qc = (lane & 3) * 2;

#pragma unroll 1
    for (int nb = 0; nb < NB_PER; nb++) {
        if (nb < NB_PER - 1) { CP_WAIT(1); } else { CP_WAIT(0); }
        __syncthreads();

        const uint32_t Abase = sb + SMEM_A_OFF;
        const uint32_t Bbase = sb + SMEM_B_OFF + (nb & 1) * 65536;

        float acc[4][4][4];
#pragma unroll
        for (int t = 0; t < 4; t++)
#pragma unroll
            for (int u = 0; u < 4; u++)
#pragma unroll
                for (int v = 0; v < 4; v++) acc[t][u][v] = 0.f;

#pragma unroll
        for (int ks = 0; ks < 16; ks++) {
            uint32_t a[4][4];
#pragma unroll
            for (int t = 0; t < 4; t++) {
                int row = warp_m * 64 + t * 16 + (lane & 15);
                int c = ks * 2 + (lane >> 4);
                ldsm_x4(a[t], Abase + row * 512 + ((c ^ (row & 7)) * 16));
            }
            uint32_t b[2][4];
#pragma unroll
            for (int p = 0; p < 2; p++) {
                int row = warp_n * 32 + p * 16 + (lane & 7) + ((lane >> 4) & 1) * 8;
                int c = ks * 2 + ((lane >> 3) & 1);
                ldsm_x4(b[p], Bbase + row * 512 + ((c ^ (row & 7)) * 16));
            }
#pragma unroll
            for (int t = 0; t < 4; t++)
#pragma unroll
                for (int u = 0; u < 4; u++)
                    mma_bf16(acc[t][u], a[t], &b[u >> 1][(u & 1) * 2]);
        }
        __syncthreads();   // all warps done reading this B buffer

        // Prefetch B block nb+2 of this half into the freed buffer.
        if (nb + 2 < NB_PER) {
            const __nv_bfloat16* Bsrc = g_eb + (size_t)(n0 + (nb + 2) * 128) * DIM;
            uint32_t Bdst = sb + SMEM_B_OFF + (nb & 1) * 65536;
            for (int i = tid; i < 4096; i += 256) {
                int row = i >> 5, c = i & 31;
                cp_async16(Bdst + row * 512 + ((c ^ (row & 7)) * 16),
                           Bsrc + row * DIM + c * 8);
            }
            CP_COMMIT();
        }

        // Epilogue: d = xn + en - 2*dot -> fp16 (overlaps with prefetch).
#pragma unroll
        for (int t = 0; t < 4; t++) {
            int r0 = warp_m * 64 + t * 16 + grp;
            int r1 = r0 + 8;
            float xn0 = s_xn[r0], xn1 = s_xn[r1];
#pragma unroll
            for (int u = 0; u < 4; u++) {
                int nl = nb * 128 + warp_n * 32 + u * 8 + qc;
                int ng = n0 + nl;
                float en0 = s_en[nl], en1 = s_en[nl + 1];
                float d0 = fmaf(-2.f, acc[t][u][0], xn0 + en0);
                float d1 = fmaf(-2.f, acc[t][u][1], xn0 + en1);
                float d2 = fmaf(-2.f, acc[t][u][2], xn1 + en0);
                float d3 = fmaf(-2.f, acc[t][u][3], xn1 + en1);
                *(__half2*)(g_dist_h + (size_t)(m0 + r0) * NEMB + ng) = __floats2half2_rn(d0, d1);
                *(__half2*)(g_dist_h + (size_t)(m0 + r1) * NEMB + ng) = __floats2half2_rn(d2, d3);
            }
        }
    }
}

// ---------------------------------------------------------------------------
// Select + refine + outputs. One warp per row (round-3/8 winner), except the
// onehot zeros are pre-filled by zero_onehot_kernel -> only the single 1.0
// is written here. Saves 268 MB of select-phase writes.
// ---------------------------------------------------------------------------
__global__ __launch_bounds__(256) void select_output_kernel(const float* __restrict__ x,
                                                            const float* __restrict__ Emb,
                                                            float* __restrict__ out) {
    const int wid = threadIdx.x >> 5, lane = threadIdx.x & 31;
    const int m = blockIdx.x * 8 + wid;

    __shared__ int s_cnt[8];
    __shared__ int s_cand[8][16];
    if (lane == 0) s_cnt[wid] = 0;
    __syncwarp();

    // Row's 1024 fp16 distances: 4 x uint4 per lane (8 halves each).
    const uint4* dp = (const uint4*)(g_dist_h + (size_t)m * NEMB);
    uint4 dv[4];
    unsigned long long bk = 0xFFFFFFFFFFFFFFFFULL;
#pragma unroll
    for (int i = 0; i < 4; i++) {
        int f = lane + i * 32;
        dv[i] = dp[f];
#pragma unroll
        for (int c = 0; c < 4; c++) {
            float2 f2 = __half22float2(((const __half2*)&dv[i])[c]);
            int col = f * 8 + c * 2;
            float v0 = fmaxf(f2.x, 0.f), v1 = fmaxf(f2.y, 0.f);
            unsigned long long k0 = ((unsigned long long)__float_as_uint(v0) << 32) | (unsigned)col;
            unsigned long long k1 = ((unsigned long long)__float_as_uint(v1) << 32) | (unsigned)(col + 1);
            bk = k0 < bk ? k0 : bk;
            bk = k1 < bk ? k1 : bk;
        }
    }
#pragma unroll
    for (int o = 16; o; o >>= 1) {
        unsigned long long t = __shfl_xor_sync(0xFFFFFFFFu, bk, o);
        bk = t < bk ? t : bk;
    }
    const float thr = __uint_as_float((unsigned)(bk >> 32)) + MARGIN;

    // Collect candidates within margin.
#pragma unroll
    for (int i = 0; i < 4; i++) {
        int f = lane + i * 32;
#pragma unroll
        for (int c = 0; c < 4; c++) {
            float2 f2 = __half22float2(((const __half2*)&dv[i])[c]);
            int col = f * 8 + c * 2;
            if (f2.x <= thr) {
                int pos = atomicAdd(&s_cnt[wid], 1);
                if (pos < 16) s_cand[wid][pos] = col;
            }
            if (f2.y <= thr) {
                int pos = atomicAdd(&s_cnt[wid], 1);
                if (pos < 16) s_cand[wid][pos] = col + 1;
            }
        }
    }
    __syncwarp();
    const int cnt = s_cnt[wid];
    const bool fallback = cnt > 16;      // rare; exact full scan
    const int ncand = fallback ? NEMB : cnt;

    const float4* xr = (const float4*)(x + (size_t)m * DIM);
    float4 xv0 = xr[lane], xv1 = xr[lane + 32];
    const float xn = g_xnorm[m];

    unsigned long long best = 0xFFFFFFFFFFFFFFFFULL;
    for (int t = 0; t < ncand; t++) {
        const int col = fallback ? t : s_cand[wid][t];
        const float4* er = (const float4*)(Emb + (size_t)col * DIM);
        float4 e0 = er[lane], e1 = er[lane + 32];
        float p = 0.f;
        p = fmaf(xv0.x, e0.x, p); p = fmaf(xv0.y, e0.y, p);
        p = fmaf(xv0.z, e0.z, p); p = fmaf(xv0.w, e0.w, p);
        p = fmaf(xv1.x, e1.x, p); p = fmaf(xv1.y, e1.y, p);
        p = fmaf(xv1.z, e1.z, p); p = fmaf(xv1.w, e1.w, p);
#pragma unroll
        for (int o = 16; o; o >>= 1) p += __shfl_xor_sync(0xFFFFFFFFu, p, o);
        float d = fmaxf(xn + g_enorm[col] - 2.f * p, 0.f);
        unsigned long long key = ((unsigned long long)__float_as_uint(d) << 32) | (unsigned)col;
        best = key < best ? key : best;
    }
    const unsigned idx = (unsigned)(best & 0xFFFFFFFFULL);

    // Outputs: loss | quantized_st | onehot hot element (zeros pre-filled).
    const float4* er = (const float4*)(Emb + (size_t)idx * DIM);
    float4* lossp = (float4*)out + (size_t)m * (DIM / 4);
    float4* qp    = (float4*)(out + (size_t)B_ROWS * DIM) + (size_t)m * (DIM / 4);

#pragma unroll
    for (int i = 0; i < 2; i++) {
        int f = lane + i * 32;
        float4 xvv = (i == 0) ? xv0 : xv1;
        float4 ev = er[f];
        float4 dl, ls, q;
        dl.x = ev.x - xvv.x; dl.y = ev.y - xvv.y; dl.z = ev.z - xvv.z; dl.w = ev.w - xvv.w;
        q.x = xvv.x + dl.x; q.y = xvv.y + dl.y; q.z = xvv.z + dl.z; q.w = xvv.w + dl.w;
        ls.x = 0.25f * dl.x * dl.x; ls.y = 0.25f * dl.y * dl.y;
        ls.z = 0.25f * dl.z * dl.z; ls.w = 0.25f * dl.w * dl.w;
        lossp[f] = ls;
        qp[f] = q;
    }
    if (lane == 0)
        out[2ull * B_ROWS * DIM + (size_t)m * NEMB + idx] = 1.0f;
}

// ---------------------------------------------------------------------------
extern "C" void kernel_launch(void* const* d_in, const int* in_sizes, int n_in,
                              void* d_out, int out_size) {
    const float* x;
    const float* e;
    if (in_sizes[0] == B_ROWS * DIM) {
        x = (const float*)d_in[0];
        e = (const float*)d_in[1];
    } else {
        x = (const float*)d_in[1];
        e = (const float*)d_in[0];
    }
    float* out = (float*)d_out;

    static cudaStream_t s2 = nullptr;
    static cudaEvent_t ev_p = nullptr, ev_z = nullptr;
    static bool init_done = false;
    if (!init_done) {
        cudaFuncSetAttribute(gemm_dist_kernel,
                             cudaFuncAttributeMaxDynamicSharedMemorySize, GEMM_SMEM);
        cudaStreamCreateWithFlags(&s2, cudaStreamNonBlocking);
        cudaEventCreateWithFlags(&ev_p, cudaEventDisableTiming);
        cudaEventCreateWithFlags(&ev_z, cudaEventDisableTiming);
        init_done = true;
    }

    prep_kernel<<<(B_ROWS + NEMB) / 8, 256>>>(x, e);

    // Fork: zero the onehot region (268 MB) on s2, overlapping the GEMM
    // (tensor-bound, DRAM ~5-20%, 16K regs/SM free for co-residency).
    const int ZGRID = (B_ROWS * NEMB / 4) / 2048;   // 8192 CTAs, 8 float4 each
    bool forked = (s2 != nullptr) && (ev_p != nullptr) && (ev_z != nullptr);
    if (forked && cudaEventRecord(ev_p, 0) != cudaSuccess) forked = false;
    if (forked && cudaStreamWaitEvent(s2, ev_p, 0) != cudaSuccess) forked = false;
    if (forked) {
        zero_onehot_kernel<<<ZGRID, 256, 0, s2>>>(out);
        if (cudaGetLastError() != cudaSuccess) forked = false;
    }
    if (!forked)
        zero_onehot_kernel<<<ZGRID, 256>>>(out);   // sequential fallback

    dim3 ggrid(B_ROWS / 128, NSPLIT);   // 512 x 2 = 1024 CTAs
    gemm_dist_kernel<<<ggrid, 256, GEMM_SMEM>>>();

    if (forked) {
        cudaEventRecord(ev_z, s2);
        cudaStreamWaitEvent(0, ev_z, 0);
    }

    select_output_kernel<<<B_ROWS / 8, 256>>>(x, e, out);
}

// round 13
// speedup vs baseline: 1.3623x; 1.0034x over previous
#include <cuda_runtime.h>
#include <cuda_bf16.h>
#include <cuda_fp16.h>
#include <cstdint>

#define B_ROWS 65536
#define DIM    256
#define NEMB   1024
#define MARGIN 2.0f
#define NSPLIT 2
#define NB_PER 4          // 8 N-blocks / NSPLIT

// ---------------------------------------------------------------------------
// Scratch (__device__ globals; no allocations)
// ---------------------------------------------------------------------------
__device__ float          g_xnorm[B_ROWS];
__device__ float          g_enorm[NEMB];
__device__ __nv_bfloat16  g_xb[(size_t)B_ROWS * DIM];
__device__ __nv_bfloat16  g_eb[(size_t)NEMB * DIM];
__device__ __half         g_dist_h[(size_t)B_ROWS * NEMB];   // 134 MB approx distances

// ---------------------------------------------------------------------------
// PTX helpers (arch-agnostic sm_80 features only)
// ---------------------------------------------------------------------------
__device__ __forceinline__ uint32_t smem_u32(const void* p) {
    uint32_t a;
    asm("{ .reg .u64 t; cvta.to.shared.u64 t, %1; cvt.u32.u64 %0, t; }" : "=r"(a) : "l"(p));
    return a;
}
__device__ __forceinline__ void cp_async16(uint32_t dst, const void* src) {
    asm volatile("cp.async.cg.shared.global [%0], [%1], 16;" :: "r"(dst), "l"(src));
}
#define CP_COMMIT() asm volatile("cp.async.commit_group;" ::: "memory")
#define CP_WAIT(n)  asm volatile("cp.async.wait_group %0;" :: "n"(n) : "memory")

__device__ __forceinline__ void ldsm_x4(uint32_t* r, uint32_t addr) {
    asm volatile("ldmatrix.sync.aligned.m8n8.x4.shared.b16 {%0,%1,%2,%3}, [%4];"
                 : "=r"(r[0]), "=r"(r[1]), "=r"(r[2]), "=r"(r[3]) : "r"(addr) : "memory");
}
__device__ __forceinline__ void mma_bf16(float* c, const uint32_t* a, const uint32_t* b) {
    asm volatile("mma.sync.aligned.m16n8k16.row.col.f32.bf16.bf16.f32 "
                 "{%0,%1,%2,%3}, {%4,%5,%6,%7}, {%8,%9}, {%0,%1,%2,%3};"
                 : "+f"(c[0]), "+f"(c[1]), "+f"(c[2]), "+f"(c[3])
                 : "r"(a[0]), "r"(a[1]), "r"(a[2]), "r"(a[3]), "r"(b[0]), "r"(b[1]));
}

// ---------------------------------------------------------------------------
// Prep: fp32 -> bf16 + exact fp32 row norms. One warp per row; blocks past
// the x range handle the embedding rows.
// ---------------------------------------------------------------------------
__global__ void prep_kernel(const float* __restrict__ x, const float* __restrict__ e) {
    int gw = blockIdx.x * 8 + (threadIdx.x >> 5);
    int lane = threadIdx.x & 31;
    const float* src;
    uint2* dst;
    float* nrm;
    if (gw < B_ROWS) {
        src = x + (size_t)gw * DIM;
        dst = (uint2*)(g_xb + (size_t)gw * DIM);
        nrm = g_xnorm + gw;
    } else {
        int m = gw - B_ROWS;
        if (m >= NEMB) return;
        src = e + (size_t)m * DIM;
        dst = (uint2*)(g_eb + (size_t)m * DIM);
        nrm = g_enorm + m;
    }
    const float4* sr = (const float4*)src;
    float s = 0.f;
#pragma unroll
    for (int i = 0; i < 2; i++) {
        int f = lane + i * 32;
        float4 v = sr[f];
        s += v.x * v.x + v.y * v.y + v.z * v.z + v.w * v.w;
        __nv_bfloat162 lo = __floats2bfloat162_rn(v.x, v.y);
        __nv_bfloat162 hi = __floats2bfloat162_rn(v.z, v.w);
        uint2 pk;
        pk.x = *(unsigned*)&lo; pk.y = *(unsigned*)&hi;
        dst[f] = pk;
    }
#pragma unroll
    for (int o = 16; o; o >>= 1) s += __shfl_xor_sync(0xFFFFFFFFu, s, o);
    if (lane == 0) *nrm = s;
}

// ---------------------------------------------------------------------------
// bf16 HMMA GEMM: approx distances -> fp16, PLUS fused onehot zero-fill.
// Grid = (512, 2) as in the round-8 winner. Each CTA additionally zeroes its
// 262 KB slice of the onehot output region, 16 STG.128/thread per nb-block —
// fire-and-forget stores draining through the GEMM's idle DRAM path (ncu:
// GEMM DRAM ~5-20%, issue ~50%). Replaces the 33 us standalone zero kernel
// (stream-fork overlap proved non-functional in rounds 9 and 12).
// ---------------------------------------------------------------------------
#define SMEM_A_OFF  0
#define SMEM_B_OFF  65536
#define SMEM_EN_OFF 196608
#define SMEM_XN_OFF 200704
#define GEMM_SMEM   201216

__global__ __launch_bounds__(256, 1) void gemm_dist_kernel(float* __restrict__ out) {
    extern __shared__ char smem[];
    const uint32_t sb = smem_u32(smem);
    const int tid = threadIdx.x, lane = tid & 31, wid = tid >> 5;
    const int warp_m = wid >> 2, warp_n = wid & 3;
    const int m0 = blockIdx.x * 128;
    const int n0 = blockIdx.y * (NEMB / NSPLIT);

    float* s_en = (float*)(smem + SMEM_EN_OFF);
    float* s_xn = (float*)(smem + SMEM_XN_OFF);
    for (int i = tid; i < NEMB / NSPLIT; i += 256) s_en[i] = g_enorm[n0 + i];
    if (tid < 128) s_xn[tid] = g_xnorm[m0 + tid];

    // Onehot zero slice for this CTA: 16384 float4 (262 KB), 4096 per nb.
    const int cta_id = blockIdx.y * (B_ROWS / 128) + blockIdx.x;   // 0..1023
    float4* ozero = (float4*)(out + 2ull * B_ROWS * DIM) +
                    (size_t)cta_id * 16384 + tid;
    const float4 zf4 = make_float4(0.f, 0.f, 0.f, 0.f);

    // A tile (once) + B blocks 0,1 of this half (two cp.async groups)
    {
        const __nv_bfloat16* Asrc = g_xb + (size_t)m0 * DIM;
        const __nv_bfloat16* Bsrc = g_eb + (size_t)n0 * DIM;
        for (int i = tid; i < 4096; i += 256) {
            int row = i >> 5, c = i & 31;
            cp_async16(sb + SMEM_A_OFF + row * 512 + ((c ^ (row & 7)) * 16),
                       Asrc + row * DIM + c * 8);
        }
        for (int i = tid; i < 4096; i += 256) {
            int row = i >> 5, c = i & 31;
            cp_async16(sb + SMEM_B_OFF + row * 512 + ((c ^ (row & 7)) * 16),
                       Bsrc + row * DIM + c * 8);
        }
        CP_COMMIT();
        for (int i = tid; i < 4096; i += 256) {
            int row = i >> 5, c = i & 31;
            cp_async16(sb + SMEM_B_OFF + 65536 + row * 512 + ((c ^ (row & 7)) * 16),
                       Bsrc + 128 * DIM + row * DIM + c * 8);
        }
        CP_COMMIT();
    }

    const int grp = lane >> 2, qc = (lane & 3) * 2;

#pragma unroll 1
    for (int nb = 0; nb < NB_PER; nb++) {
        if (nb < NB_PER - 1) { CP_WAIT(1); } else { CP_WAIT(0); }
        __syncthreads();

        const uint32_t Abase = sb + SMEM_A_OFF;
        const uint32_t Bbase = sb + SMEM_B_OFF + (nb & 1) * 65536;

        float acc[4][4][4];
#pragma unroll
        for (int t = 0; t < 4; t++)
#pragma unroll
            for (int u = 0; u < 4; u++)
#pragma unroll
                for (int v = 0; v < 4; v++) acc[t][u][v] = 0.f;

#pragma unroll
        for (int ks = 0; ks < 16; ks++) {
            uint32_t a[4][4];
#pragma unroll
            for (int t = 0; t < 4; t++) {
                int row = warp_m * 64 + t * 16 + (lane & 15);
                int c = ks * 2 + (lane >> 4);
                ldsm_x4(a[t], Abase + row * 512 + ((c ^ (row & 7)) * 16));
            }
            uint32_t b[2][4];
#pragma unroll
            for (int p = 0; p < 2; p++) {
                int row = warp_n * 32 + p * 16 + (lane & 7) + ((lane >> 4) & 1) * 8;
                int c = ks * 2 + ((lane >> 3) & 1);
                ldsm_x4(b[p], Bbase + row * 512 + ((c ^ (row & 7)) * 16));
            }
#pragma unroll
            for (int t = 0; t < 4; t++)
#pragma unroll
                for (int u = 0; u < 4; u++)
                    mma_bf16(acc[t][u], a[t], &b[u >> 1][(u & 1) * 2]);
        }
        __syncthreads();   // all warps done reading this B buffer

        // Prefetch B block nb+2 of this half into the freed buffer.
        if (nb + 2 < NB_PER) {
            const __nv_bfloat16* Bsrc = g_eb + (size_t)(n0 + (nb + 2) * 128) * DIM;
            uint32_t Bdst = sb + SMEM_B_OFF + (nb & 1) * 65536;
            for (int i = tid; i < 4096; i += 256) {
                int row = i >> 5, c = i & 31;
                cp_async16(Bdst + row * 512 + ((c ^ (row & 7)) * 16),
                           Bsrc + row * DIM + c * 8);
            }
            CP_COMMIT();
        }

        // Fused onehot zero-fill: 16 coalesced float4 stores per thread.
        {
            float4* oz = ozero + (size_t)nb * 4096;
#pragma unroll
            for (int k = 0; k < 16; k++) oz[(size_t)k * 256] = zf4;
        }

        // Epilogue: d = xn + en - 2*dot -> fp16 (overlaps with prefetch).
#pragma unroll
        for (int t = 0; t < 4; t++) {
            int r0 = warp_m * 64 + t * 16 + grp;
            int r1 = r0 + 8;
            float xn0 = s_xn[r0], xn1 = s_xn[r1];
#pragma unroll
            for (int u = 0; u < 4; u++) {
                int nl = nb * 128 + warp_n * 32 + u * 8 + qc;
                int ng = n0 + nl;
                float en0 = s_en[nl], en1 = s_en[nl + 1];
                float d0 = fmaf(-2.f, acc[t][u][0], xn0 + en0);
                float d1 = fmaf(-2.f, acc[t][u][1], xn0 + en1);
                float d2 = fmaf(-2.f, acc[t][u][2], xn1 + en0);
                float d3 = fmaf(-2.f, acc[t][u][3], xn1 + en1);
                *(__half2*)(g_dist_h + (size_t)(m0 + r0) * NEMB + ng) = __floats2half2_rn(d0, d1);
                *(__half2*)(g_dist_h + (size_t)(m0 + r1) * NEMB + ng) = __floats2half2_rn(d2, d3);
            }
        }
    }
}

// ---------------------------------------------------------------------------
// Select + refine + outputs. One warp per row; onehot zeros were pre-filled
// by the GEMM, so only loss | quantized_st | the single 1.0 are written here.
// ---------------------------------------------------------------------------
__global__ __launch_bounds__(256) void select_output_kernel(const float* __restrict__ x,
                                                            const float* __restrict__ Emb,
                                                            float* __restrict__ out) {
    const int wid = threadIdx.x >> 5, lane = threadIdx.x & 31;
    const int m = blockIdx.x * 8 + wid;

    __shared__ int s_cnt[8];
    __shared__ int s_cand[8][16];
    if (lane == 0) s_cnt[wid] = 0;
    __syncwarp();

    // Row's 1024 fp16 distances: 4 x uint4 per lane (8 halves each).
    const uint4* dp = (const uint4*)(g_dist_h + (size_t)m * NEMB);
    uint4 dv[4];
    unsigned long long bk = 0xFFFFFFFFFFFFFFFFULL;
#pragma unroll
    for (int i = 0; i < 4; i++) {
        int f = lane + i * 32;
        dv[i] = dp[f];
#pragma unroll
        for (int c = 0; c < 4; c++) {
            float2 f2 = __half22float2(((const __half2*)&dv[i])[c]);
            int col = f * 8 + c * 2;
            float v0 = fmaxf(f2.x, 0.f), v1 = fmaxf(f2.y, 0.f);
            unsigned long long k0 = ((unsigned long long)__float_as_uint(v0) << 32) | (unsigned)col;
            unsigned long long k1 = ((unsigned long long)__float_as_uint(v1) << 32) | (unsigned)(col + 1);
            bk = k0 < bk ? k0 : bk;
            bk = k1 < bk ? k1 : bk;
        }
    }
#pragma unroll
    for (int o = 16; o; o >>= 1) {
        unsigned long long t = __shfl_xor_sync(0xFFFFFFFFu, bk, o);
        bk = t < bk ? t : bk;
    }
    const float thr = __uint_as_float((unsigned)(bk >> 32)) + MARGIN;

    // Collect candidates within margin.
#pragma unroll
    for (int i = 0; i < 4; i++) {
        int f = lane + i * 32;
#pragma unroll
        for (int c = 0; c < 4; c++) {
            float2 f2 = __half22float2(((const __half2*)&dv[i])[c]);
            int col = f * 8 + c * 2;
            if (f2.x <= thr) {
                int pos = atomicAdd(&s_cnt[wid], 1);
                if (pos < 16) s_cand[wid][pos] = col;
            }
            if (f2.y <= thr) {
                int pos = atomicAdd(&s_cnt[wid], 1);
                if (pos < 16) s_cand[wid][pos] = col + 1;
            }
        }
    }
    __syncwarp();
    const int cnt = s_cnt[wid];
    const bool fallback = cnt > 16;      // rare; exact full scan
    const int ncand = fallback ? NEMB : cnt;

    const float4* xr = (const float4*)(x + (size_t)m * DIM);
    float4 xv0 = xr[lane], xv1 = xr[lane + 32];
    const float xn = g_xnorm[m];

    unsigned long long best = 0xFFFFFFFFFFFFFFFFULL;
    for (int t = 0; t < ncand; t++) {
        const int col = fallback ? t : s_cand[wid][t];
        const float4* er = (const float4*)(Emb + (size_t)col * DIM);
        float4 e0 = er[lane], e1 = er[lane + 32];
        float p = 0.f;
        p = fmaf(xv0.x, e0.x, p); p = fmaf(xv0.y, e0.y, p);
        p = fmaf(xv0.z, e0.z, p); p = fmaf(xv0.w, e0.w, p);
        p = fmaf(xv1.x, e1.x, p); p = fmaf(xv1.y, e1.y, p);
        p = fmaf(xv1.z, e1.z, p); p = fmaf(xv1.w, e1.w, p);
#pragma unroll
        for (int o = 16; o; o >>= 1) p += __shfl_xor_sync(0xFFFFFFFFu, p, o);
        float d = fmaxf(xn + g_enorm[col] - 2.f * p, 0.f);
        unsigned long long key = ((unsigned long long)__float_as_uint(d) << 32) | (unsigned)col;
        best = key < best ? key : best;
    }
    const unsigned idx = (unsigned)(best & 0xFFFFFFFFULL);

    // Outputs: loss | quantized_st | onehot hot element (zeros pre-filled).
    const float4* er = (const float4*)(Emb + (size_t)idx * DIM);
    float4* lossp = (float4*)out + (size_t)m * (DIM / 4);
    float4* qp    = (float4*)(out + (size_t)B_ROWS * DIM) + (size_t)m * (DIM / 4);

#pragma unroll
    for (int i = 0; i < 2; i++) {
        int f = lane + i * 32;
        float4 xvv = (i == 0) ? xv0 : xv1;
        float4 ev = er[f];
        float4 dl, ls, q;
        dl.x = ev.x - xvv.x; dl.y = ev.y - xvv.y; dl.z = ev.z - xvv.z; dl.w = ev.w - xvv.w;
        q.x = xvv.x + dl.x; q.y = xvv.y + dl.y; q.z = xvv.z + dl.z; q.w = xvv.w + dl.w;
        ls.x = 0.25f * dl.x * dl.x; ls.y = 0.25f * dl.y * dl.y;
        ls.z = 0.25f * dl.z * dl.z; ls.w = 0.25f * dl.w * dl.w;
        lossp[f] = ls;
        qp[f] = q;
    }
    if (lane == 0)
        out[2ull * B_ROWS * DIM + (size_t)m * NEMB + idx] = 1.0f;
}

// ---------------------------------------------------------------------------
extern "C" void kernel_launch(void* const* d_in, const int* in_sizes, int n_in,
                              void* d_out, int out_size) {
    const float* x;
    const float* e;
    if (in_sizes[0] == B_ROWS * DIM) {
        x = (const float*)d_in[0];
        e = (const float*)d_in[1];
    } else {
        x = (const float*)d_in[1];
        e = (const float*)d_in[0];
    }
    float* out = (float*)d_out;

    static bool init_done = false;
    if (!init_done) {
        cudaFuncSetAttribute(gemm_dist_kernel,
                             cudaFuncAttributeMaxDynamicSharedMemorySize, GEMM_SMEM);
        init_done = true;
    }

    prep_kernel<<<(B_ROWS + NEMB) / 8, 256>>>(x, e);

    dim3 ggrid(B_ROWS / 128, NSPLIT);   // 512 x 2 = 1024 CTAs
    gemm_dist_kernel<<<ggrid, 256, GEMM_SMEM>>>(out);

    select_output_kernel<<<B_ROWS / 8, 256>>>(x, e, out);
}

// round 14
// speedup vs baseline: 1.3899x; 1.0202x over previous
#include <cuda_runtime.h>
#include <cuda_bf16.h>
#include <cuda_fp16.h>
#include <cstdint>
#include <math_constants.h>

#define B_ROWS 65536
#define DIM    256
#define NEMB   1024
#define MARGIN 2.0f
#define NSPLIT 2
#define NB_PER 4          // 8 N-blocks / NSPLIT

// ---------------------------------------------------------------------------
// Scratch (__device__ globals; no allocations)
// ---------------------------------------------------------------------------
__device__ float          g_xnorm[B_ROWS];
__device__ float          g_enorm[NEMB];
__device__ __nv_bfloat16  g_xb[(size_t)B_ROWS * DIM];
__device__ __nv_bfloat16  g_eb[(size_t)NEMB * DIM];
__device__ __half         g_dist_h[(size_t)B_ROWS * NEMB];  // 134 MB approx distances
__device__ float          g_bmin[(size_t)B_ROWS * 8];       // per-row per-128-block min

// ---------------------------------------------------------------------------
// PTX helpers (arch-agnostic sm_80 features only)
// ---------------------------------------------------------------------------
__device__ __forceinline__ uint32_t smem_u32(const void* p) {
    uint32_t a;
    asm("{ .reg .u64 t; cvta.to.shared.u64 t, %1; cvt.u32.u64 %0, t; }" : "=r"(a) : "l"(p));
    return a;
}
__device__ __forceinline__ void cp_async16(uint32_t dst, const void* src) {
    asm volatile("cp.async.cg.shared.global [%0], [%1], 16;" :: "r"(dst), "l"(src));
}
#define CP_COMMIT() asm volatile("cp.async.commit_group;" ::: "memory")
#define CP_WAIT(n)  asm volatile("cp.async.wait_group %0;" :: "n"(n) : "memory")

__device__ __forceinline__ void ldsm_x4(uint32_t* r, uint32_t addr) {
    asm volatile("ldmatrix.sync.aligned.m8n8.x4.shared.b16 {%0,%1,%2,%3}, [%4];"
                 : "=r"(r[0]), "=r"(r[1]), "=r"(r[2]), "=r"(r[3]) : "r"(addr) : "memory");
}
__device__ __forceinline__ void mma_bf16(float* c, const uint32_t* a, const uint32_t* b) {
    asm volatile("mma.sync.aligned.m16n8k16.row.col.f32.bf16.bf16.f32 "
                 "{%0,%1,%2,%3}, {%4,%5,%6,%7}, {%8,%9}, {%0,%1,%2,%3};"
                 : "+f"(c[0]), "+f"(c[1]), "+f"(c[2]), "+f"(c[3])
                 : "r"(a[0]), "r"(a[1]), "r"(a[2]), "r"(a[3]), "r"(b[0]), "r"(b[1]));
}

// ---------------------------------------------------------------------------
// Prep: fp32 -> bf16 + exact fp32 row norms. One warp per row; blocks past
// the x range handle the embedding rows.
// ---------------------------------------------------------------------------
__global__ void prep_kernel(const float* __restrict__ x, const float* __restrict__ e) {
    int gw = blockIdx.x * 8 + (threadIdx.x >> 5);
    int lane = threadIdx.x & 31;
    const float* src;
    uint2* dst;
    float* nrm;
    if (gw < B_ROWS) {
        src = x + (size_t)gw * DIM;
        dst = (uint2*)(g_xb + (size_t)gw * DIM);
        nrm = g_xnorm + gw;
    } else {
        int m = gw - B_ROWS;
        if (m >= NEMB) return;
        src = e + (size_t)m * DIM;
        dst = (uint2*)(g_eb + (size_t)m * DIM);
        nrm = g_enorm + m;
    }
    const float4* sr = (const float4*)src;
    float s = 0.f;
#pragma unroll
    for (int i = 0; i < 2; i++) {
        int f = lane + i * 32;
        float4 v = sr[f];
        s += v.x * v.x + v.y * v.y + v.z * v.z + v.w * v.w;
        __nv_bfloat162 lo = __floats2bfloat162_rn(v.x, v.y);
        __nv_bfloat162 hi = __floats2bfloat162_rn(v.z, v.w);
        uint2 pk;
        pk.x = *(unsigned*)&lo; pk.y = *(unsigned*)&hi;
        dst[f] = pk;
    }
#pragma unroll
    for (int o = 16; o; o >>= 1) s += __shfl_xor_sync(0xFFFFFFFFu, s, o);
    if (lane == 0) *nrm = s;
}

// ---------------------------------------------------------------------------
// bf16 HMMA GEMM: approx distances -> fp16 + per-row per-128-block mins +
// fused onehot zero-fill. Grid (512, 2), 256 threads, warp tile 64x32
// (the round-8 winner). bmin: clamped per-block min via smem atomicMin on
// float bits (valid since clamped d >= 0) — lets select skip ~7/8 of the
// dist matrix. SMEM rows 512B, 16B chunk c at c ^ (row & 7).
// ---------------------------------------------------------------------------
#define SMEM_A_OFF    0
#define SMEM_B_OFF    65536
#define SMEM_EN_OFF   196608
#define SMEM_XN_OFF   198656
#define SMEM_BMIN_OFF 199168
#define GEMM_SMEM     201216

__global__ __launch_bounds__(256, 1) void gemm_dist_kernel(float* __restrict__ out) {
    extern __shared__ char smem[];
    const uint32_t sb = smem_u32(smem);
    const int tid = threadIdx.x, lane = tid & 31, wid = tid >> 5;
    const int warp_m = wid >> 2, warp_n = wid & 3;
    const int m0 = blockIdx.x * 128;
    const int n0 = blockIdx.y * (NEMB / NSPLIT);

    float* s_en = (float*)(smem + SMEM_EN_OFF);
    float* s_xn = (float*)(smem + SMEM_XN_OFF);
    unsigned (*s_bmin)[128] = (unsigned(*)[128])(smem + SMEM_BMIN_OFF);
    for (int i = tid; i < NEMB / NSPLIT; i += 256) s_en[i] = g_enorm[n0 + i];
    if (tid < 128) s_xn[tid] = g_xnorm[m0 + tid];
    for (int i = tid; i < NB_PER * 128; i += 256)
        ((unsigned*)(smem + SMEM_BMIN_OFF))[i] = 0x7F800000u;   // +inf

    // Onehot zero slice for this CTA: 16384 float4 (262 KB), 4096 per nb.
    const int cta_id = blockIdx.y * (B_ROWS / 128) + blockIdx.x;
    float4* ozero = (float4*)(out + 2ull * B_ROWS * DIM) +
                    (size_t)cta_id * 16384 + tid;
    const float4 zf4 = make_float4(0.f, 0.f, 0.f, 0.f);

    // A tile (once) + B blocks 0,1 of this half (two cp.async groups)
    {
        const __nv_bfloat16* Asrc = g_xb + (size_t)m0 * DIM;
        const __nv_bfloat16* Bsrc = g_eb + (size_t)n0 * DIM;
        for (int i = tid; i < 4096; i += 256) {
            int row = i >> 5, c = i & 31;
            cp_async16(sb + SMEM_A_OFF + row * 512 + ((c ^ (row & 7)) * 16),
                       Asrc + row * DIM + c * 8);
        }
        for (int i = tid; i < 4096; i += 256) {
            int row = i >> 5, c = i & 31;
            cp_async16(sb + SMEM_B_OFF + row * 512 + ((c ^ (row & 7)) * 16),
                       Bsrc + row * DIM + c * 8);
        }
        CP_COMMIT();
        for (int i = tid; i < 4096; i += 256) {
            int row = i >> 5, c = i & 31;
            cp_async16(sb + SMEM_B_OFF + 65536 + row * 512 + ((c ^ (row & 7)) * 16),
                       Bsrc + 128 * DIM + row * DIM + c * 8);
        }
        CP_COMMIT();
    }

    const int grp = lane >> 2, qc = (lane & 3) * 2;

#pragma unroll 1
    for (int nb = 0; nb < NB_PER; nb++) {
        if (nb < NB_PER - 1) { CP_WAIT(1); } else { CP_WAIT(0); }
        __syncthreads();

        const uint32_t Abase = sb + SMEM_A_OFF;
        const uint32_t Bbase = sb + SMEM_B_OFF + (nb & 1) * 65536;

        float acc[4][4][4];
#pragma unroll
        for (int t = 0; t < 4; t++)
#pragma unroll
            for (int u = 0; u < 4; u++)
#pragma unroll
                for (int v = 0; v < 4; v++) acc[t][u][v] = 0.f;

#pragma unroll
        for (int ks = 0; ks < 16; ks++) {
            uint32_t a[4][4];
#pragma unroll
            for (int t = 0; t < 4; t++) {
                int row = warp_m * 64 + t * 16 + (lane & 15);
                int c = ks * 2 + (lane >> 4);
                ldsm_x4(a[t], Abase + row * 512 + ((c ^ (row & 7)) * 16));
            }
            uint32_t b[2][4];
#pragma unroll
            for (int p = 0; p < 2; p++) {
                int row = warp_n * 32 + p * 16 + (lane & 7) + ((lane >> 4) & 1) * 8;
                int c = ks * 2 + ((lane >> 3) & 1);
                ldsm_x4(b[p], Bbase + row * 512 + ((c ^ (row & 7)) * 16));
            }
#pragma unroll
            for (int t = 0; t < 4; t++)
#pragma unroll
                for (int u = 0; u < 4; u++)
                    mma_bf16(acc[t][u], a[t], &b[u >> 1][(u & 1) * 2]);
        }
        __syncthreads();   // all warps done reading this B buffer

        // Prefetch B block nb+2 of this half into the freed buffer.
        if (nb + 2 < NB_PER) {
            const __nv_bfloat16* Bsrc = g_eb + (size_t)(n0 + (nb + 2) * 128) * DIM;
            uint32_t Bdst = sb + SMEM_B_OFF + (nb & 1) * 65536;
            for (int i = tid; i < 4096; i += 256) {
                int row = i >> 5, c = i & 31;
                cp_async16(Bdst + row * 512 + ((c ^ (row & 7)) * 16),
                           Bsrc + row * DIM + c * 8);
            }
            CP_COMMIT();
        }

        // Fused onehot zero-fill: 16 coalesced float4 stores per thread.
        {
            float4* oz = ozero + (size_t)nb * 4096;
#pragma unroll
            for (int k = 0; k < 16; k++) oz[(size_t)k * 256] = zf4;
        }

        // Epilogue: d = xn + en - 2*dot -> fp16 stores + per-block row mins.
#pragma unroll
        for (int t = 0; t < 4; t++) {
            int r0 = warp_m * 64 + t * 16 + grp;
            int r1 = r0 + 8;
            float xn0 = s_xn[r0], xn1 = s_xn[r1];
            float bm0 = CUDART_INF_F, bm1 = CUDART_INF_F;
#pragma unroll
            for (int u = 0; u < 4; u++) {
                int nl = nb * 128 + warp_n * 32 + u * 8 + qc;
                int ng = n0 + nl;
                float en0 = s_en[nl], en1 = s_en[nl + 1];
                float d0 = fmaf(-2.f, acc[t][u][0], xn0 + en0);
                float d1 = fmaf(-2.f, acc[t][u][1], xn0 + en1);
                float d2 = fmaf(-2.f, acc[t][u][2], xn1 + en0);
                float d3 = fmaf(-2.f, acc[t][u][3], xn1 + en1);
                bm0 = fminf(bm0, fminf(d0, d1));
                bm1 = fminf(bm1, fminf(d2, d3));
                *(__half2*)(g_dist_h + (size_t)(m0 + r0) * NEMB + ng) = __floats2half2_rn(d0, d1);
                *(__half2*)(g_dist_h + (size_t)(m0 + r1) * NEMB + ng) = __floats2half2_rn(d2, d3);
            }
            atomicMin(&s_bmin[nb][r0], __float_as_uint(fmaxf(bm0, 0.f)));
            atomicMin(&s_bmin[nb][r1], __float_as_uint(fmaxf(bm1, 0.f)));
        }
    }

    // Store block mins (clamped; float bits monotonic for >= 0).
    __syncthreads();
    if (tid < 128) {
        float* bp = g_bmin + (size_t)(m0 + tid) * 8 + blockIdx.y * NB_PER;
#pragma unroll
        for (int j = 0; j < NB_PER; j++)
            bp[j] = __uint_as_float(s_bmin[j][tid]);
    }
}

// ---------------------------------------------------------------------------
// Select + refine + outputs. One warp per row. Block-min pruning: read 8
// block mins, scan only blocks that can hold margin-candidates (typically 1)
// -> dist read drops 134 MB -> ~20 MB. Exact fp32 refine; onehot zeros were
// pre-filled by the GEMM, so only loss | q_st | the single 1.0 are written.
// ---------------------------------------------------------------------------
__global__ __launch_bounds__(256) void select_output_kernel(const float* __restrict__ x,
                                                            const float* __restrict__ Emb,
                                                            float* __restrict__ out) {
    const int wid = threadIdx.x >> 5, lane = threadIdx.x & 31;
    const int m = blockIdx.x * 8 + wid;

    __shared__ int s_cnt[8];
    __shared__ int s_cand[8][16];
    if (lane == 0) s_cnt[wid] = 0;
    __syncwarp();

    // Block mins -> approx row min (clamped) -> threshold + block mask.
    float b = (lane < 8) ? g_bmin[(size_t)m * 8 + lane] : CUDART_INF_F;
    float gmin = b;
#pragma unroll
    for (int o = 16; o; o >>= 1) gmin = fminf(gmin, __shfl_xor_sync(0xFFFFFFFFu, gmin, o));
    const float thr = gmin + MARGIN;
    unsigned bmask = __ballot_sync(0xFFFFFFFFu, lane < 8 && b <= thr);

    // Scan only flagged 128-col blocks for candidates.
    while (bmask) {
        int j = __ffs(bmask) - 1;
        bmask &= bmask - 1;
        const __half2* bp = (const __half2*)(g_dist_h + (size_t)m * NEMB + j * 128);
#pragma unroll
        for (int i = 0; i < 2; i++) {
            float2 f2 = __half22float2(bp[lane + i * 32]);
            int col = j * 128 + (lane + i * 32) * 2;
            if (f2.x <= thr) {
                int pos = atomicAdd(&s_cnt[wid], 1);
                if (pos < 16) s_cand[wid][pos] = col;
            }
            if (f2.y <= thr) {
                int pos = atomicAdd(&s_cnt[wid], 1);
                if (pos < 16) s_cand[wid][pos] = col + 1;
            }
        }
    }
    __syncwarp();
    const int cnt = s_cnt[wid];
    const bool fallback = cnt > 16;      // rare; exact full scan
    const int ncand = fallback ? NEMB : cnt;

    const float4* xr = (const float4*)(x + (size_t)m * DIM);
    float4 xv0 = xr[lane], xv1 = xr[lane + 32];
    const float xn = g_xnorm[m];

    unsigned long long best = 0xFFFFFFFFFFFFFFFFULL;
    for (int t = 0; t < ncand; t++) {
        const int col = fallback ? t : s_cand[wid][t];
        const float4* er = (const float4*)(Emb + (size_t)col * DIM);
        float4 e0 = er[lane], e1 = er[lane + 32];
        float p = 0.f;
        p = fmaf(xv0.x, e0.x, p); p = fmaf(xv0.y, e0.y, p);
        p = fmaf(xv0.z, e0.z, p); p = fmaf(xv0.w, e0.w, p);
        p = fmaf(xv1.x, e1.x, p); p = fmaf(xv1.y, e1.y, p);
        p = fmaf(xv1.z, e1.z, p); p = fmaf(xv1.w, e1.w, p);
#pragma unroll
        for (int o = 16; o; o >>= 1) p += __shfl_xor_sync(0xFFFFFFFFu, p, o);
        float d = fmaxf(xn + g_enorm[col] - 2.f * p, 0.f);
        unsigned long long key = ((unsigned long long)__float_as_uint(d) << 32) | (unsigned)col;
        best = key < best ? key : best;
    }
    const unsigned idx = (unsigned)(best & 0xFFFFFFFFULL);

    // Outputs: loss | quantized_st | onehot hot element (zeros pre-filled).
    const float4* er = (const float4*)(Emb + (size_t)idx * DIM);
    float4* lossp = (float4*)out + (size_t)m * (DIM / 4);
    float4* qp    = (float4*)(out + (size_t)B_ROWS * DIM) + (size_t)m * (DIM / 4);

#pragma unroll
    for (int i = 0; i < 2; i++) {
        int f = lane + i * 32;
        float4 xvv = (i == 0) ? xv0 : xv1;
        float4 ev = er[f];
        float4 dl, ls, q;
        dl.x = ev.x - xvv.x; dl.y = ev.y - xvv.y; dl.z = ev.z - xvv.z; dl.w = ev.w - xvv.w;
        q.x = xvv.x + dl.x; q.y = xvv.y + dl.y; q.z = xvv.z + dl.z; q.w = xvv.w + dl.w;
        ls.x = 0.25f * dl.x * dl.x; ls.y = 0.25f * dl.y * dl.y;
        ls.z = 0.25f * dl.z * dl.z; ls.w = 0.25f * dl.w * dl.w;
        lossp[f] = ls;
        qp[f] = q;
    }
    if (lane == 0)
        out[2ull * B_ROWS * DIM + (size_t)m * NEMB + idx] = 1.0f;
}

// ---------------------------------------------------------------------------
extern "C" void kernel_launch(void* const* d_in, const int* in_sizes, int n_in,
                              void* d_out, int out_size) {
    const float* x;
    const float* e;
    if (in_sizes[0] == B_ROWS * DIM) {
        x = (const float*)d_in[0];
        e = (const float*)d_in[1];
    } else {
        x = (const float*)d_in[1];
        e = (const float*)d_in[0];
    }
    float* out = (float*)d_out;

    static bool init_done = false;
    if (!init_done) {
        cudaFuncSetAttribute(gemm_dist_kernel,
                             cudaFuncAttributeMaxDynamicSharedMemorySize, GEMM_SMEM);
        init_done = true;
    }

    prep_kernel<<<(B_ROWS + NEMB) / 8, 256>>>(x, e);

    dim3 ggrid(B_ROWS / 128, NSPLIT);   // 512 x 2 = 1024 CTAs
    gemm_dist_kernel<<<ggrid, 256, GEMM_SMEM>>>(out);

    select_output_kernel<<<B_ROWS / 8, 256>>>(x, e, out);
}

// round 15
// speedup vs baseline: 1.4166x; 1.0192x over previous
#include <cuda_runtime.h>
#include <cuda_bf16.h>
#include <cuda_fp16.h>
#include <cstdint>
#include <math_constants.h>

#define B_ROWS 65536
#define DIM    256
#define NEMB   1024
#define MARGIN 2.0f
#define NSPLIT 2
#define NB_PER 4          // 8 N-blocks / NSPLIT

// ---------------------------------------------------------------------------
// Scratch (__device__ globals; no allocations)
// ---------------------------------------------------------------------------
__device__ float          g_xnorm[B_ROWS];
__device__ float          g_enorm[NEMB];
__device__ __nv_bfloat16  g_xb[(size_t)B_ROWS * DIM];
__device__ __nv_bfloat16  g_eb[(size_t)NEMB * DIM];
__device__ __half         g_dist_h[(size_t)B_ROWS * NEMB];  // 134 MB approx distances
__device__ float          g_bmin[(size_t)B_ROWS * 8];       // per-row per-128-block min

// ---------------------------------------------------------------------------
// PTX helpers (arch-agnostic sm_80 features only)
// ---------------------------------------------------------------------------
__device__ __forceinline__ uint32_t smem_u32(const void* p) {
    uint32_t a;
    asm("{ .reg .u64 t; cvta.to.shared.u64 t, %1; cvt.u32.u64 %0, t; }" : "=r"(a) : "l"(p));
    return a;
}
__device__ __forceinline__ void cp_async16(uint32_t dst, const void* src) {
    asm volatile("cp.async.cg.shared.global [%0], [%1], 16;" :: "r"(dst), "l"(src));
}
#define CP_COMMIT() asm volatile("cp.async.commit_group;" ::: "memory")
#define CP_WAIT(n)  asm volatile("cp.async.wait_group %0;" :: "n"(n) : "memory")

__device__ __forceinline__ void ldsm_x4(uint32_t* r, uint32_t addr) {
    asm volatile("ldmatrix.sync.aligned.m8n8.x4.shared.b16 {%0,%1,%2,%3}, [%4];"
                 : "=r"(r[0]), "=r"(r[1]), "=r"(r[2]), "=r"(r[3]) : "r"(addr) : "memory");
}
__device__ __forceinline__ void mma_bf16(float* c, const uint32_t* a, const uint32_t* b) {
    asm volatile("mma.sync.aligned.m16n8k16.row.col.f32.bf16.bf16.f32 "
                 "{%0,%1,%2,%3}, {%4,%5,%6,%7}, {%8,%9}, {%0,%1,%2,%3};"
                 : "+f"(c[0]), "+f"(c[1]), "+f"(c[2]), "+f"(c[3])
                 : "r"(a[0]), "r"(a[1]), "r"(a[2]), "r"(a[3]), "r"(b[0]), "r"(b[1]));
}

// ---------------------------------------------------------------------------
// Prep: fp32 -> bf16 + exact fp32 row norms. One warp per row; blocks past
// the x range handle the embedding rows.
// ---------------------------------------------------------------------------
__global__ void prep_kernel(const float* __restrict__ x, const float* __restrict__ e) {
    int gw = blockIdx.x * 8 + (threadIdx.x >> 5);
    int lane = threadIdx.x & 31;
    const float* src;
    uint2* dst;
    float* nrm;
    if (gw < B_ROWS) {
        src = x + (size_t)gw * DIM;
        dst = (uint2*)(g_xb + (size_t)gw * DIM);
        nrm = g_xnorm + gw;
    } else {
        int m = gw - B_ROWS;
        if (m >= NEMB) return;
        src = e + (size_t)m * DIM;
        dst = (uint2*)(g_eb + (size_t)m * DIM);
        nrm = g_enorm + m;
    }
    const float4* sr = (const float4*)src;
    float s = 0.f;
#pragma unroll
    for (int i = 0; i < 2; i++) {
        int f = lane + i * 32;
        float4 v = sr[f];
        s += v.x * v.x + v.y * v.y + v.z * v.z + v.w * v.w;
        __nv_bfloat162 lo = __floats2bfloat162_rn(v.x, v.y);
        __nv_bfloat162 hi = __floats2bfloat162_rn(v.z, v.w);
        uint2 pk;
        pk.x = *(unsigned*)&lo; pk.y = *(unsigned*)&hi;
        dst[f] = pk;
    }
#pragma unroll
    for (int o = 16; o; o >>= 1) s += __shfl_xor_sync(0xFFFFFFFFu, s, o);
    if (lane == 0) *nrm = s;
}

// ---------------------------------------------------------------------------
// bf16 HMMA GEMM: approx distances -> fp16 + per-row per-128-block mins +
// fused onehot zero-fill. Grid (512, 2), 256 threads, warp tile 64x32.
// ROUND-15 CHANGE: the per-nb epilogue (dist stores + bmin + zero-fill) runs
// BEFORE the B-buffer-reuse barrier, so fast warps drain stores while slow
// warps still issue MMAs instead of all 8 warps storing in lockstep after
// the barrier (ncu: tensor ~47%, epilogue ~600 issue-cyc vs 1024 MMA-cyc).
// ---------------------------------------------------------------------------
#define SMEM_A_OFF    0
#define SMEM_B_OFF    65536
#define SMEM_EN_OFF   196608
#define SMEM_XN_OFF   198656
#define SMEM_BMIN_OFF 199168
#define GEMM_SMEM     201216

__global__ __launch_bounds__(256, 1) void gemm_dist_kernel(float* __restrict__ out) {
    extern __shared__ char smem[];
    const uint32_t sb = smem_u32(smem);
    const int tid = threadIdx.x, lane = tid & 31, wid = tid >> 5;
    const int warp_m = wid >> 2, warp_n = wid & 3;
    const int m0 = blockIdx.x * 128;
    const int n0 = blockIdx.y * (NEMB / NSPLIT);

    float* s_en = (float*)(smem + SMEM_EN_OFF);
    float* s_xn = (float*)(smem + SMEM_XN_OFF);
    unsigned (*s_bmin)[128] = (unsigned(*)[128])(smem + SMEM_BMIN_OFF);
    for (int i = tid; i < NEMB / NSPLIT; i += 256) s_en[i] = g_enorm[n0 + i];
    if (tid < 128) s_xn[tid] = g_xnorm[m0 + tid];
    for (int i = tid; i < NB_PER * 128; i += 256)
        ((unsigned*)(smem + SMEM_BMIN_OFF))[i] = 0x7F800000u;   // +inf

    // Onehot zero slice for this CTA: 16384 float4 (262 KB), 4096 per nb.
    const int cta_id = blockIdx.y * (B_ROWS / 128) + blockIdx.x;
    float4* ozero = (float4*)(out + 2ull * B_ROWS * DIM) +
                    (size_t)cta_id * 16384 + tid;
    const float4 zf4 = make_float4(0.f, 0.f, 0.f, 0.f);

    // A tile (once) + B blocks 0,1 of this half (two cp.async groups)
    {
        const __nv_bfloat16* Asrc = g_xb + (size_t)m0 * DIM;
        const __nv_bfloat16* Bsrc = g_eb + (size_t)n0 * DIM;
        for (int i = tid; i < 4096; i += 256) {
            int row = i >> 5, c = i & 31;
            cp_async16(sb + SMEM_A_OFF + row * 512 + ((c ^ (row & 7)) * 16),
                       Asrc + row * DIM + c * 8);
        }
        for (int i = tid; i < 4096; i += 256) {
            int row = i >> 5, c = i & 31;
            cp_async16(sb + SMEM_B_OFF + row * 512 + ((c ^ (row & 7)) * 16),
                       Bsrc + row * DIM + c * 8);
        }
        CP_COMMIT();
        for (int i = tid; i < 4096; i += 256) {
            int row = i >> 5, c = i & 31;
            cp_async16(sb + SMEM_B_OFF + 65536 + row * 512 + ((c ^ (row & 7)) * 16),
                       Bsrc + 128 * DIM + row * DIM + c * 8);
        }
        CP_COMMIT();
    }

    const int grp = lane >> 2, qc = (lane & 3) * 2;

#pragma unroll 1
    for (int nb = 0; nb < NB_PER; nb++) {
        if (nb < NB_PER - 1) { CP_WAIT(1); } else { CP_WAIT(0); }
        __syncthreads();

        const uint32_t Abase = sb + SMEM_A_OFF;
        const uint32_t Bbase = sb + SMEM_B_OFF + (nb & 1) * 65536;

        float acc[4][4][4];
#pragma unroll
        for (int t = 0; t < 4; t++)
#pragma unroll
            for (int u = 0; u < 4; u++)
#pragma unroll
                for (int v = 0; v < 4; v++) acc[t][u][v] = 0.f;

#pragma unroll
        for (int ks = 0; ks < 16; ks++) {
            uint32_t a[4][4];
#pragma unroll
            for (int t = 0; t < 4; t++) {
                int row = warp_m * 64 + t * 16 + (lane & 15);
                int c = ks * 2 + (lane >> 4);
                ldsm_x4(a[t], Abase + row * 512 + ((c ^ (row & 7)) * 16));
            }
            uint32_t b[2][4];
#pragma unroll
            for (int p = 0; p < 2; p++) {
                int row = warp_n * 32 + p * 16 + (lane & 7) + ((lane >> 4) & 1) * 8;
                int c = ks * 2 + ((lane >> 3) & 1);
                ldsm_x4(b[p], Bbase + row * 512 + ((c ^ (row & 7)) * 16));
            }
#pragma unroll
            for (int t = 0; t < 4; t++)
#pragma unroll
                for (int u = 0; u < 4; u++)
                    mma_bf16(acc[t][u], a[t], &b[u >> 1][(u & 1) * 2]);
        }

        // --- Epilogue BEFORE the barrier: overlaps other warps' MMAs ---

        // Fused onehot zero-fill: 16 coalesced float4 stores per thread.
        {
            float4* oz = ozero + (size_t)nb * 4096;
#pragma unroll
            for (int k = 0; k < 16; k++) oz[(size_t)k * 256] = zf4;
        }

        // d = xn + en - 2*dot -> fp16 stores + per-block row mins.
#pragma unroll
        for (int t = 0; t < 4; t++) {
            int r0 = warp_m * 64 + t * 16 + grp;
            int r1 = r0 + 8;
            float xn0 = s_xn[r0], xn1 = s_xn[r1];
            float bm0 = CUDART_INF_F, bm1 = CUDART_INF_F;
#pragma unroll
            for (int u = 0; u < 4; u++) {
                int nl = nb * 128 + warp_n * 32 + u * 8 + qc;
                int ng = n0 + nl;
                float en0 = s_en[nl], en1 = s_en[nl + 1];
                float d0 = fmaf(-2.f, acc[t][u][0], xn0 + en0);
                float d1 = fmaf(-2.f, acc[t][u][1], xn0 + en1);
                float d2 = fmaf(-2.f, acc[t][u][2], xn1 + en0);
                float d3 = fmaf(-2.f, acc[t][u][3], xn1 + en1);
                bm0 = fminf(bm0, fminf(d0, d1));
                bm1 = fminf(bm1, fminf(d2, d3));
                *(__half2*)(g_dist_h + (size_t)(m0 + r0) * NEMB + ng) = __floats2half2_rn(d0, d1);
                *(__half2*)(g_dist_h + (size_t)(m0 + r1) * NEMB + ng) = __floats2half2_rn(d2, d3);
            }
            atomicMin(&s_bmin[nb][r0], __float_as_uint(fmaxf(bm0, 0.f)));
            atomicMin(&s_bmin[nb][r1], __float_as_uint(fmaxf(bm1, 0.f)));
        }

        __syncthreads();   // all warps done reading this B buffer

        // Prefetch B block nb+2 of this half into the freed buffer.
        if (nb + 2 < NB_PER) {
            const __nv_bfloat16* Bsrc = g_eb + (size_t)(n0 + (nb + 2) * 128) * DIM;
            uint32_t Bdst = sb + SMEM_B_OFF + (nb & 1) * 65536;
            for (int i = tid; i < 4096; i += 256) {
                int row = i >> 5, c = i & 31;
                cp_async16(Bdst + row * 512 + ((c ^ (row & 7)) * 16),
                           Bsrc + row * DIM + c * 8);
            }
            CP_COMMIT();
        }
    }

    // Store block mins (clamped; float bits monotonic for >= 0).
    __syncthreads();
    if (tid < 128) {
        float* bp = g_bmin + (size_t)(m0 + tid) * 8 + blockIdx.y * NB_PER;
#pragma unroll
        for (int j = 0; j < NB_PER; j++)
            bp[j] = __uint_as_float(s_bmin[j][tid]);
    }
}

// ---------------------------------------------------------------------------
// Select + refine + outputs. One warp per row. Block-min pruning: read 8
// block mins, scan only blocks that can hold margin-candidates (typically 1).
// Exact fp32 refine; onehot zeros pre-filled by the GEMM, so only
// loss | q_st | the single 1.0 are written.
// ---------------------------------------------------------------------------
__global__ __launch_bounds__(256) void select_output_kernel(const float* __restrict__ x,
                                                            const float* __restrict__ Emb,
                                                            float* __restrict__ out) {
    const int wid = threadIdx.x >> 5, lane = threadIdx.x & 31;
    const int m = blockIdx.x * 8 + wid;

    __shared__ int s_cnt[8];
    __shared__ int s_cand[8][16];
    if (lane == 0) s_cnt[wid] = 0;
    __syncwarp();

    // Block mins -> approx row min (clamped) -> threshold + block mask.
    float b = (lane < 8) ? g_bmin[(size_t)m * 8 + lane] : CUDART_INF_F;
    float gmin = b;
#pragma unroll
    for (int o = 16; o; o >>= 1) gmin = fminf(gmin, __shfl_xor_sync(0xFFFFFFFFu, gmin, o));
    const float thr = gmin + MARGIN;
    unsigned bmask = __ballot_sync(0xFFFFFFFFu, lane < 8 && b <= thr);

    // Scan only flagged 128-col blocks for candidates.
    while (bmask) {
        int j = __ffs(bmask) - 1;
        bmask &= bmask - 1;
        const __half2* bp = (const __half2*)(g_dist_h + (size_t)m * NEMB + j * 128);
#pragma unroll
        for (int i = 0; i < 2; i++) {
            float2 f2 = __half22float2(bp[lane + i * 32]);
            int col = j * 128 + (lane + i * 32) * 2;
            if (f2.x <= thr) {
                int pos = atomicAdd(&s_cnt[wid], 1);
                if (pos < 16) s_cand[wid][pos] = col;
            }
            if (f2.y <= thr) {
                int pos = atomicAdd(&s_cnt[wid], 1);
                if (pos < 16) s_cand[wid][pos] = col + 1;
            }
        }
    }
    __syncwarp();
    const int cnt = s_cnt[wid];
    const bool fallback = cnt > 16;      // rare; exact full scan
    const int ncand = fallback ? NEMB : cnt;

    const float4* xr = (const float4*)(x + (size_t)m * DIM);
    float4 xv0 = xr[lane], xv1 = xr[lane + 32];
    const float xn = g_xnorm[m];

    unsigned long long best = 0xFFFFFFFFFFFFFFFFULL;
    for (int t = 0; t < ncand; t++) {
        const int col = fallback ? t : s_cand[wid][t];
        const float4* er = (const float4*)(Emb + (size_t)col * DIM);
        float4 e0 = er[lane], e1 = er[lane + 32];
        float p = 0.f;
        p = fmaf(xv0.x, e0.x, p); p = fmaf(xv0.y, e0.y, p);
        p = fmaf(xv0.z, e0.z, p); p = fmaf(xv0.w, e0.w, p);
        p = fmaf(xv1.x, e1.x, p); p = fmaf(xv1.y, e1.y, p);
        p = fmaf(xv1.z, e1.z, p); p = fmaf(xv1.w, e1.w, p);
#pragma unroll
        for (int o = 16; o; o >>= 1) p += __shfl_xor_sync(0xFFFFFFFFu, p, o);
        float d = fmaxf(xn + g_enorm[col] - 2.f * p, 0.f);
        unsigned long long key = ((unsigned long long)__float_as_uint(d) << 32) | (unsigned)col;
        best = key < best ? key : best;
    }
    const unsigned idx = (unsigned)(best & 0xFFFFFFFFULL);

    // Outputs: loss | quantized_st | onehot hot element (zeros pre-filled).
    const float4* er = (const float4*)(Emb + (size_t)idx * DIM);
    float4* lossp = (float4*)out + (size_t)m * (DIM / 4);
    float4* qp    = (float4*)(out + (size_t)B_ROWS * DIM) + (size_t)m * (DIM / 4);

#pragma unroll
    for (int i = 0; i < 2; i++) {
        int f = lane + i * 32;
        float4 xvv = (i == 0) ? xv0 : xv1;
        float4 ev = er[f];
        float4 dl, ls, q;
        dl.x = ev.x - xvv.x; dl.y = ev.y - xvv.y; dl.z = ev.z - xvv.z; dl.w = ev.w - xvv.w;
        q.x = xvv.x + dl.x; q.y = xvv.y + dl.y; q.z = xvv.z + dl.z; q.w = xvv.w + dl.w;
        ls.x = 0.25f * dl.x * dl.x; ls.y = 0.25f * dl.y * dl.y;
        ls.z = 0.25f * dl.z * dl.z; ls.w = 0.25f * dl.w * dl.w;
        lossp[f] = ls;
        qp[f] = q;
    }
    if (lane == 0)
        out[2ull * B_ROWS * DIM + (size_t)m * NEMB + idx] = 1.0f;
}

// ---------------------------------------------------------------------------
extern "C" void kernel_launch(void* const* d_in, const int* in_sizes, int n_in,
                              void* d_out, int out_size) {
    const float* x;
    const float* e;
    if (in_sizes[0] == B_ROWS * DIM) {
        x = (const float*)d_in[0];
        e = (const float*)d_in[1];
    } else {
        x = (const float*)d_in[1];
        e = (const float*)d_in[0];
    }
    float* out = (float*)d_out;

    static bool init_done = false;
    if (!init_done) {
        cudaFuncSetAttribute(gemm_dist_kernel,
                             cudaFuncAttributeMaxDynamicSharedMemorySize, GEMM_SMEM);
        init_done = true;
    }

    prep_kernel<<<(B_ROWS + NEMB) / 8, 256>>>(x, e);

    dim3 ggrid(B_ROWS / 128, NSPLIT);   // 512 x 2 = 1024 CTAs
    gemm_dist_kernel<<<ggrid, 256, GEMM_SMEM>>>(out);

    select_output_kernel<<<B_ROWS / 8, 256>>>(x, e, out);
}